// round 7
// baseline (speedup 1.0000x reference)
#include <cuda_runtime.h>

// Problem constants
#define BB 2048
#define SS 512
#define DD 128
#define HH 64
#define H4 16
#define OO 8

// Scratch (device globals — no runtime allocation allowed)
__device__ float g_z1[BB * H4];
__device__ float g_mu1[HH], g_rs1[HH];
__device__ float g_mu2[H4], g_rs2[H4];

// ---------------------------------------------------------------------------
// Packed f32x2 FMA: d = {fma(a.lo,b.lo,d.lo), fma(a.hi,b.hi,d.hi)}
// ---------------------------------------------------------------------------
__device__ __forceinline__ void fma2(unsigned long long& d,
                                     unsigned long long a,
                                     unsigned long long b) {
    asm("fma.rn.f32x2 %0, %1, %2, %0;" : "+l"(d) : "l"(a), "l"(b));
}
__device__ __forceinline__ float f2lo(unsigned long long v) {
    return __uint_as_float((unsigned)(v & 0xffffffffull));
}
__device__ __forceinline__ float f2hi(unsigned long long v) {
    return __uint_as_float((unsigned)(v >> 32));
}

// ---------------------------------------------------------------------------
// k1: fused input projection + ReLU RNN recurrence with packed f32x2 FMAs.
//
// Grid 128 CTAs x 128 threads, CTA owns 16 batch rows. Warp w specializes in
// j in [16w, 16w+16) for ALL 16 rows (weights staged once per SM, no per-warp
// duplication). Lane = (rg = lane>>3, jg = lane&7): handles rows {rg, rg+4,
// rg+8, rg+12} x j-pair {16w+2jg, 16w+2jg+1}. Accumulators are f32x2 packed
// along the d/k reduction dim (even/odd partial sums, combined at the end),
// so both FMA operands load as natural 64-bit halves of LDS.128 — no packing
// instructions. h is cross-warp -> 2 __syncthreads per step.
// ---------------------------------------------------------------------------
#define K1_THREADS 128
#define K1_ROWS 16
#define K1_GRID (BB / K1_ROWS)   // 128
#define XS 132                   // padded s_x row stride (floats): 132%32=4 -> conflict-free
#define HS 68                    // padded s_h row stride (floats): 68%32=4  -> conflict-free
// smem: wih 32KB + whh 16KB + x 8448B + h 4352B
#define K1_SMEM (2048*16 + 1024*16 + K1_ROWS*XS*4 + K1_ROWS*HS*4)

__global__ void __launch_bounds__(K1_THREADS, 1)
rnn_fused_kernel(const float* __restrict__ x, const float* __restrict__ h0,
                 const float* __restrict__ Wih, const float* __restrict__ Whh,
                 const float* __restrict__ bih, const float* __restrict__ bhh,
                 float* __restrict__ hT_out) {
    extern __shared__ float smem[];
    float4* s_wih = (float4*)smem;            // [(w*32+d4)*16 + slot]  slot=(jl>>1)|((jl&1)<<3)
    float4* s_whh = s_wih + 2048;             // [(w*16+k4)*16 + slot]
    float*  s_x   = (float*)(s_whh + 1024);   // [16 r][XS]
    float*  s_h   = s_x + K1_ROWS * XS;       // [16 r][HS]

    const int tid  = threadIdx.x;
    const int warp = tid >> 5;
    const int lane = tid & 31;
    const int jg   = lane & 7;   // j-pair group within warp's 16-j slab
    const int rg   = lane >> 3;  // row sub-index: rows = 4k + rg

    // Stage W_ih: value = Wih[row = 16w+jl][4*d4 .. 4*d4+3], slot-reordered so
    // the pair-0 quads (jl even) occupy slots 0..7 and pair-1 quads slots 8..15
    // -> both weight LDS.128 hit 8 consecutive float4s (conflict-free).
    for (int idx = tid; idx < 2048; idx += K1_THREADS) {
        int w = idx >> 9, rem = idx & 511, d4 = rem >> 4, jl = rem & 15;
        int slot = (jl >> 1) | ((jl & 1) << 3);
        s_wih[(w * 32 + d4) * 16 + slot] = *(const float4*)(Wih + (w * 16 + jl) * DD + d4 * 4);
    }
    for (int idx = tid; idx < 1024; idx += K1_THREADS) {
        int w = idx >> 8, rem = idx & 255, k4 = rem >> 4, jl = rem & 15;
        int slot = (jl >> 1) | ((jl & 1) << 3);
        s_whh[(w * 16 + k4) * 16 + slot] = *(const float4*)(Whh + (w * 16 + jl) * HH + k4 * 4);
    }

    const int bBase = blockIdx.x * K1_ROWS;

    // init h(t=-1) = h0
    for (int idx = tid; idx < K1_ROWS * HH; idx += K1_THREADS) {
        int r = idx >> 6, j = idx & 63;
        s_h[r * HS + j] = h0[(bBase + r) * HH + j];
    }

    // bias for this lane's two j outputs, packed into acc lo-half (hi = +0)
    const int j0 = warp * 16 + 2 * jg;
    const unsigned long long bj0 = (unsigned long long)__float_as_uint(bih[j0] + bhh[j0]);
    const unsigned long long bj1 = (unsigned long long)__float_as_uint(bih[j0 + 1] + bhh[j0 + 1]);

    // x staging: thread (warp,lane) loads rows {warp, warp+4, warp+8, warp+12},
    // quad d4 = lane. Per-warp global reads are 512B contiguous (one row).
    const float* xp[4];
    float4 xr[4];
#pragma unroll
    for (int k = 0; k < 4; k++) {
        xp[k] = x + (size_t)(bBase + 4 * k + warp) * (SS * DD) + lane * 4;
        xr[k] = *(const float4*)xp[k];                         // t = 0
        *(float4*)(s_x + (4 * k + warp) * XS + lane * 4) = xr[k];
    }
    __syncthreads();

    const ulonglong2* wih_b = (const ulonglong2*)s_wih + warp * 512 + jg;
    const ulonglong2* whh_b = (const ulonglong2*)s_whh + warp * 256 + jg;

    for (int t = 0; t < SS; t++) {
        // prefetch x(t+1) early — latency hidden under ~1536 cyc of FMA
        if (t + 1 < SS) {
#pragma unroll
            for (int k = 0; k < 4; k++)
                xr[k] = *(const float4*)(xp[k] + (size_t)(t + 1) * DD);
        }

        unsigned long long a0[4], a1[4];   // (even-d partial, odd-d partial)
#pragma unroll
        for (int k = 0; k < 4; k++) { a0[k] = bj0; a1[k] = bj1; }

        // input projection: 32 d-quads
#pragma unroll
        for (int d4 = 0; d4 < 32; d4++) {
            ulonglong2 w0 = wih_b[d4 * 16];      // W[j0][d..d+3] as 2 pairs
            ulonglong2 w1 = wih_b[d4 * 16 + 8];  // W[j0+1][d..d+3]
#pragma unroll
            for (int k = 0; k < 4; k++) {
                ulonglong2 xv = *(const ulonglong2*)(s_x + (4 * k + rg) * XS + d4 * 4);
                fma2(a0[k], xv.x, w0.x);
                fma2(a0[k], xv.y, w0.y);
                fma2(a1[k], xv.x, w1.x);
                fma2(a1[k], xv.y, w1.y);
            }
        }
        // recurrence: 16 k-quads
#pragma unroll
        for (int k4 = 0; k4 < 16; k4++) {
            ulonglong2 w0 = whh_b[k4 * 16];
            ulonglong2 w1 = whh_b[k4 * 16 + 8];
#pragma unroll
            for (int k = 0; k < 4; k++) {
                ulonglong2 hv = *(const ulonglong2*)(s_h + (4 * k + rg) * HS + k4 * 4);
                fma2(a0[k], hv.x, w0.x);
                fma2(a0[k], hv.y, w0.y);
                fma2(a1[k], hv.x, w1.x);
                fma2(a1[k], hv.y, w1.y);
            }
        }

        __syncthreads();   // everyone done reading s_x(t), s_h(t-1)

#pragma unroll
        for (int k = 0; k < 4; k++) {
            float v0 = fmaxf(f2lo(a0[k]) + f2hi(a0[k]), 0.0f);
            float v1 = fmaxf(f2lo(a1[k]) + f2hi(a1[k]), 0.0f);
            *(float2*)(s_h + (4 * k + rg) * HS + j0) = make_float2(v0, v1);
        }
        if (t + 1 < SS) {
#pragma unroll
            for (int k = 0; k < 4; k++)
                *(float4*)(s_x + (4 * k + warp) * XS + lane * 4) = xr[k];
        }
        __syncthreads();   // h(t), x(t+1) visible
    }

    // s_h now holds hT
    for (int idx = tid; idx < K1_ROWS * HH; idx += K1_THREADS) {
        int r = idx >> 6, j = idx & 63;
        hT_out[(bBase + r) * HH + j] = s_h[r * HS + j];
    }
}

// ---------------------------------------------------------------------------
// k2: BatchNorm1d stats over hT (two-pass, deterministic tree reduce).
// One CTA per feature (64 CTAs x 256 threads).
// ---------------------------------------------------------------------------
__global__ void bn1_stats_kernel(const float* __restrict__ hT) {
    const int f = blockIdx.x, tid = threadIdx.x;
    __shared__ float red[256];
    __shared__ float s_mu;

    float s = 0.0f;
    for (int b = tid; b < BB; b += 256) s += hT[b * HH + f];
    red[tid] = s;
    __syncthreads();
    for (int w = 128; w > 0; w >>= 1) {
        if (tid < w) red[tid] += red[tid + w];
        __syncthreads();
    }
    if (tid == 0) s_mu = red[0] * (1.0f / BB);
    __syncthreads();
    const float mu = s_mu;

    float s2 = 0.0f;
    for (int b = tid; b < BB; b += 256) {
        float v = hT[b * HH + f] - mu;
        s2 += v * v;
    }
    red[tid] = s2;
    __syncthreads();
    for (int w = 128; w > 0; w >>= 1) {
        if (tid < w) red[tid] += red[tid + w];
        __syncthreads();
    }
    if (tid == 0) {
        g_mu1[f] = mu;
        g_rs1[f] = rsqrtf(red[0] * (1.0f / BB) + 1e-5f);
    }
}

// ---------------------------------------------------------------------------
// k3: z1 = relu(BN1(hT) @ fc1_W^T + fc1_b). Thread per batch row.
// ---------------------------------------------------------------------------
__global__ void fc1_kernel(const float* __restrict__ hT,
                           const float* __restrict__ g1, const float* __restrict__ be1,
                           const float* __restrict__ fW, const float* __restrict__ fb) {
    __shared__ float sW[H4 * HH];
    __shared__ float sc[HH], sh[HH], sb[H4];
    const int tid = threadIdx.x;
    for (int i = tid; i < H4 * HH; i += 256) sW[i] = fW[i];
    if (tid < HH) {
        float s = g_rs1[tid] * g1[tid];
        sc[tid] = s;
        sh[tid] = be1[tid] - g_mu1[tid] * s;
    }
    if (tid < H4) sb[tid] = fb[tid];
    __syncthreads();

    const int b = blockIdx.x * 256 + tid;
    float acc[H4];
#pragma unroll
    for (int o = 0; o < H4; o++) acc[o] = sb[o];
#pragma unroll 8
    for (int j = 0; j < HH; j++) {
        float v = fmaf(hT[b * HH + j], sc[j], sh[j]);
#pragma unroll
        for (int o = 0; o < H4; o++) acc[o] = fmaf(v, sW[o * HH + j], acc[o]);
    }
#pragma unroll
    for (int o = 0; o < H4; o++) g_z1[b * H4 + o] = fmaxf(acc[o], 0.0f);
}

// ---------------------------------------------------------------------------
// k4: BatchNorm stats over z1 — coalesced one-pass (sum + sumsq), 256 threads.
// Each thread reads full 16-float rows (4x float4, coalesced), deterministic
// shfl tree + fixed-order cross-warp combine.
// ---------------------------------------------------------------------------
__global__ void bn2_stats_kernel() {
    __shared__ float rs[8][H4], rq[8][H4];
    const int tid = threadIdx.x, lane = tid & 31, w = tid >> 5;

    float s[H4], q[H4];
#pragma unroll
    for (int i = 0; i < H4; i++) { s[i] = 0.0f; q[i] = 0.0f; }

    for (int b = tid; b < BB; b += 256) {
        const float4* p = (const float4*)(g_z1 + b * H4);
#pragma unroll
        for (int u = 0; u < 4; u++) {
            float4 v = p[u];
            s[u*4+0] += v.x; q[u*4+0] += v.x * v.x;
            s[u*4+1] += v.y; q[u*4+1] += v.y * v.y;
            s[u*4+2] += v.z; q[u*4+2] += v.z * v.z;
            s[u*4+3] += v.w; q[u*4+3] += v.w * v.w;
        }
    }
#pragma unroll
    for (int i = 0; i < H4; i++) {
#pragma unroll
        for (int d = 16; d > 0; d >>= 1) {
            s[i] += __shfl_xor_sync(0xFFFFFFFFu, s[i], d);
            q[i] += __shfl_xor_sync(0xFFFFFFFFu, q[i], d);
        }
    }
    if (lane == 0) {
#pragma unroll
        for (int i = 0; i < H4; i++) { rs[w][i] = s[i]; rq[w][i] = q[i]; }
    }
    __syncthreads();
    if (tid < H4) {
        float S = 0.0f, Q = 0.0f;
#pragma unroll
        for (int w2 = 0; w2 < 8; w2++) { S += rs[w2][tid]; Q += rq[w2][tid]; }
        float mu = S * (1.0f / BB);
        g_mu2[tid] = mu;
        g_rs2[tid] = rsqrtf(fmaxf(Q * (1.0f / BB) - mu * mu, 0.0f) + 1e-5f);
    }
}

// ---------------------------------------------------------------------------
// k5: out = BN2(z1) @ fc2_W^T + fc2_b. Thread per batch row.
// ---------------------------------------------------------------------------
__global__ void fc2_kernel(const float* __restrict__ g2, const float* __restrict__ be2,
                           const float* __restrict__ fW, const float* __restrict__ fb,
                           float* __restrict__ out) {
    __shared__ float sW[OO * H4];
    __shared__ float sc[H4], sh[H4], sb[OO];
    const int tid = threadIdx.x;
    if (tid < OO * H4) sW[tid] = fW[tid];
    if (tid < H4) {
        float s = g_rs2[tid] * g2[tid];
        sc[tid] = s;
        sh[tid] = be2[tid] - g_mu2[tid] * s;
    }
    if (tid < OO) sb[tid] = fb[tid];
    __syncthreads();

    const int b = blockIdx.x * 256 + tid;
    float z[H4];
#pragma unroll
    for (int o = 0; o < H4; o++) z[o] = fmaf(g_z1[b * H4 + o], sc[o], sh[o]);
#pragma unroll
    for (int c = 0; c < OO; c++) {
        float a = sb[c];
#pragma unroll
        for (int o = 0; o < H4; o++) a = fmaf(z[o], sW[c * H4 + o], a);
        out[b * OO + c] = a;
    }
}

// ---------------------------------------------------------------------------
// Launch. Output layout (reference returns (out, hT[None])):
//   d_out[0 .. B*O)                : out  [2048, 8]
//   d_out[B*O .. B*O + B*H)        : hT   [1, 2048, 64]
// ---------------------------------------------------------------------------
extern "C" void kernel_launch(void* const* d_in, const int* in_sizes, int n_in,
                              void* d_out, int out_size) {
    const float* x    = (const float*)d_in[0];
    const float* h0   = (const float*)d_in[1];
    const float* Wih  = (const float*)d_in[2];
    const float* Whh  = (const float*)d_in[3];
    const float* bih  = (const float*)d_in[4];
    const float* bhh  = (const float*)d_in[5];
    const float* bn1g = (const float*)d_in[6];
    const float* bn1b = (const float*)d_in[7];
    const float* fc1W = (const float*)d_in[8];
    const float* fc1b = (const float*)d_in[9];
    const float* bn2g = (const float*)d_in[10];
    const float* bn2b = (const float*)d_in[11];
    const float* fc2W = (const float*)d_in[12];
    const float* fc2b = (const float*)d_in[13];

    float* out = (float*)d_out;
    float* hT  = out + BB * OO;

    cudaFuncSetAttribute(rnn_fused_kernel,
                         cudaFuncAttributeMaxDynamicSharedMemorySize, K1_SMEM);

    rnn_fused_kernel<<<K1_GRID, K1_THREADS, K1_SMEM>>>(x, h0, Wih, Whh, bih, bhh, hT);
    bn1_stats_kernel<<<HH, 256>>>(hT);
    fc1_kernel<<<BB / 256, 256>>>(hT, bn1g, bn1b, fc1W, fc1b);
    bn2_stats_kernel<<<1, 256>>>();
    fc2_kernel<<<BB / 256, 256>>>(bn2g, bn2b, fc2W, fc2b, out);
}

// round 12
// speedup vs baseline: 1.4006x; 1.4006x over previous
#include <cuda_runtime.h>
#include <cstdint>

// Problem constants
#define BB 2048
#define SS 512
#define DD 128
#define HH 64
#define H4 16
#define OO 8

// Scratch (device globals — no runtime allocation allowed)
__device__ float g_xp[(size_t)BB * SS * HH];   // [B*S][H]: x@Wih^T + b_ih + b_hh
__device__ float g_z1[BB * H4];
__device__ float g_mu1[HH], g_rs1[HH];
__device__ float g_mu2[H4], g_rs2[H4];

// ===========================================================================
// bf16 split helpers
// ===========================================================================
// pack {hi=bf16(b), lo=bf16(a)} and the bf16-rounded residual pair
__device__ __forceinline__ void split_pair(float a, float b, uint32_t& h, uint32_t& l) {
    asm("cvt.rn.bf16x2.f32 %0, %1, %2;" : "=r"(h) : "f"(b), "f"(a));
    float ra = a - __uint_as_float(h << 16);
    float rb = b - __uint_as_float(h & 0xffff0000u);
    asm("cvt.rn.bf16x2.f32 %0, %1, %2;" : "=r"(l) : "f"(rb), "f"(ra));
}

__device__ __forceinline__ void mma_bf16(float c[4], const uint32_t a[4],
                                         uint32_t b0, uint32_t b1) {
    asm volatile(
        "mma.sync.aligned.m16n8k16.row.col.f32.bf16.bf16.f32 "
        "{%0,%1,%2,%3}, {%4,%5,%6,%7}, {%8,%9}, {%0,%1,%2,%3};"
        : "+f"(c[0]), "+f"(c[1]), "+f"(c[2]), "+f"(c[3])
        : "r"(a[0]), "r"(a[1]), "r"(a[2]), "r"(a[3]), "r"(b0), "r"(b1));
}

// ===========================================================================
// k0: xp GEMM — xp[row,:] = x[row,:] @ Wih^T + (b_ih + b_hh), rows = B*S.
// bf16 2-way split (3 products) on mma.sync m16n8k16 (base PTX, no 'a' feat).
// Persistent grid 296 CTAs x 128 threads (2 CTAs/SM). CTA tile = 128 rows.
// Warp covers 32 rows (2 m-tiles) x N=64 (8 n-tiles) x K=128 (8 k-steps).
// W fragments precomputed once per CTA into a 32KB smem table; one LDS.128
// per (k,n) yields {Bh0,Bh1,Bl0,Bl1} for 6 MMAs (3 products x 2 m-tiles).
// ===========================================================================
#define G_THREADS 128
#define G_GRID 296
#define TM 128
#define NTILES ((BB * SS) / TM)   // 8192

__global__ void __launch_bounds__(G_THREADS, 2)
xp_gemm_kernel(const float* __restrict__ x, const float* __restrict__ Wih,
               const float* __restrict__ bih, const float* __restrict__ bhh) {
    __shared__ uint4 s_tab[2048];   // [(k*8+n)*32 + lane] = {Bh0,Bh1,Bl0,Bl1}
    __shared__ float s_bias[HH];

    const int tid  = threadIdx.x;
    const int warp = tid >> 5;
    const int lane = tid & 31;
    const int g    = lane >> 2;        // l/4
    const int qb   = (lane & 3) * 2;   // (l%4)*2

    // --- build W fragment table (once per persistent CTA) ---
    for (int e = tid; e < 2048; e += G_THREADS) {
        int k  = e >> 8;
        int n  = (e >> 5) & 7;
        int ln = e & 31;
        const float* wp = Wih + (n * 8 + (ln >> 2)) * DD + k * 16 + (ln & 3) * 2;
        float w0 = wp[0], w1 = wp[1], w8 = wp[8], w9 = wp[9];
        uint4 v;
        split_pair(w0, w1, v.x, v.z);
        split_pair(w8, w9, v.y, v.w);
        s_tab[e] = v;
    }
    if (tid < HH) s_bias[tid] = bih[tid] + bhh[tid];
    __syncthreads();

    // per-lane bias pairs for each n-tile (epilogue cols = n*8 + qb, +1)
    float2 biasn[8];
#pragma unroll
    for (int n = 0; n < 8; n++)
        biasn[n] = make_float2(s_bias[n * 8 + qb], s_bias[n * 8 + qb + 1]);

    for (int tile = blockIdx.x; tile < NTILES; tile += G_GRID) {
        const size_t row0 = (size_t)tile * TM + warp * 32;   // warp's first row
        const float* x0 = x + (row0 + g) * DD;               // m-tile 0, row g
        const float* x1 = x + (row0 + 16 + g) * DD;          // m-tile 1, row g

        float c[2][8][4];
#pragma unroll
        for (int mt = 0; mt < 2; mt++)
#pragma unroll
            for (int n = 0; n < 8; n++)
#pragma unroll
                for (int i = 0; i < 4; i++) c[mt][n][i] = 0.0f;

#pragma unroll
        for (int k = 0; k < 8; k++) {
            const int cc = k * 16 + qb;
            uint32_t ah0[4], al0[4], ah1[4], al1[4];
            {
                float2 p0 = *(const float2*)(x0 + cc);
                float2 p1 = *(const float2*)(x0 + 8 * DD + cc);
                float2 p2 = *(const float2*)(x0 + cc + 8);
                float2 p3 = *(const float2*)(x0 + 8 * DD + cc + 8);
                split_pair(p0.x, p0.y, ah0[0], al0[0]);
                split_pair(p1.x, p1.y, ah0[1], al0[1]);
                split_pair(p2.x, p2.y, ah0[2], al0[2]);
                split_pair(p3.x, p3.y, ah0[3], al0[3]);
            }
            {
                float2 p0 = *(const float2*)(x1 + cc);
                float2 p1 = *(const float2*)(x1 + 8 * DD + cc);
                float2 p2 = *(const float2*)(x1 + cc + 8);
                float2 p3 = *(const float2*)(x1 + 8 * DD + cc + 8);
                split_pair(p0.x, p0.y, ah1[0], al1[0]);
                split_pair(p1.x, p1.y, ah1[1], al1[1]);
                split_pair(p2.x, p2.y, ah1[2], al1[2]);
                split_pair(p3.x, p3.y, ah1[3], al1[3]);
            }
#pragma unroll
            for (int n = 0; n < 8; n++) {
                uint4 w = s_tab[(k * 8 + n) * 32 + lane];
                mma_bf16(c[0][n], ah0, w.x, w.y);   // Ah*Bh
                mma_bf16(c[0][n], al0, w.x, w.y);   // Al*Bh
                mma_bf16(c[0][n], ah0, w.z, w.w);   // Ah*Bl
                mma_bf16(c[1][n], ah1, w.x, w.y);
                mma_bf16(c[1][n], al1, w.x, w.y);
                mma_bf16(c[1][n], ah1, w.z, w.w);
            }
        }

        // epilogue: C frag rows = l/4 (+8), cols = n*8 + qb (+1)
#pragma unroll
        for (int mt = 0; mt < 2; mt++) {
            const size_t rbase = row0 + mt * 16 + g;
#pragma unroll
            for (int n = 0; n < 8; n++) {
                float* op = g_xp + rbase * HH + n * 8 + qb;
                *(float2*)op =
                    make_float2(c[mt][n][0] + biasn[n].x, c[mt][n][1] + biasn[n].y);
                *(float2*)(op + 8 * HH) =
                    make_float2(c[mt][n][2] + biasn[n].x, c[mt][n][3] + biasn[n].y);
            }
        }
    }
}

// ===========================================================================
// k1: recurrence only — h = relu(xp[t] + h @ Whh^T), xp streamed from g_xp.
// 128 CTAs x 128 threads, warp-private 4 rows, no cross-warp sync.
// ===========================================================================
#define R_THREADS 128
#define R_GRID 128

__global__ void __launch_bounds__(R_THREADS, 1)
rnn_rec_kernel(const float* __restrict__ h0, const float* __restrict__ Whh,
               float* __restrict__ hT_out) {
    __shared__ float4 s_w[16 * 64];   // [kq][j]: Whh[j][4kq..4kq+3]
    __shared__ float s_h[16][68];     // padded rows

    const int tid = threadIdx.x;
    const int warp = tid >> 5;
    const int lane = tid & 31;

    for (int idx = tid; idx < 1024; idx += R_THREADS) {
        int kq = idx >> 6, j = idx & 63;
        s_w[idx] = *(const float4*)(Whh + j * HH + kq * 4);
    }
    const int gb0 = blockIdx.x * 16;
    for (int idx = tid; idx < 16 * HH; idx += R_THREADS) {
        int r = idx >> 6, j = idx & 63;
        s_h[r][j] = h0[(gb0 + r) * HH + j];
    }
    __syncthreads();

    const int r0 = warp * 4;          // warp-private rows r0..r0+3
    const float* xb[4];
    float cur0[4], cur1[4], nx0[4], nx1[4];
#pragma unroll
    for (int r = 0; r < 4; r++) {
        xb[r] = g_xp + (size_t)(gb0 + r0 + r) * SS * HH;
        cur0[r] = xb[r][lane];
        cur1[r] = xb[r][lane + 32];
    }

    for (int t = 0; t < SS; t++) {
        if (t + 1 < SS) {
            const int o = (t + 1) * HH;
#pragma unroll
            for (int r = 0; r < 4; r++) {
                nx0[r] = xb[r][o + lane];
                nx1[r] = xb[r][o + lane + 32];
            }
        }
        float a0[4], a1[4];
#pragma unroll
        for (int r = 0; r < 4; r++) { a0[r] = cur0[r]; a1[r] = cur1[r]; }

#pragma unroll 4
        for (int kq = 0; kq < 16; kq++) {
            float4 w0 = s_w[kq * 64 + lane];
            float4 w1 = s_w[kq * 64 + lane + 32];
#pragma unroll
            for (int r = 0; r < 4; r++) {
                float4 hv = *(const float4*)(&s_h[r0 + r][kq * 4]);
                a0[r] = fmaf(hv.x, w0.x, a0[r]);
                a0[r] = fmaf(hv.y, w0.y, a0[r]);
                a0[r] = fmaf(hv.z, w0.z, a0[r]);
                a0[r] = fmaf(hv.w, w0.w, a0[r]);
                a1[r] = fmaf(hv.x, w1.x, a1[r]);
                a1[r] = fmaf(hv.y, w1.y, a1[r]);
                a1[r] = fmaf(hv.z, w1.z, a1[r]);
                a1[r] = fmaf(hv.w, w1.w, a1[r]);
            }
        }
        __syncwarp();
#pragma unroll
        for (int r = 0; r < 4; r++) {
            s_h[r0 + r][lane]      = fmaxf(a0[r], 0.0f);
            s_h[r0 + r][lane + 32] = fmaxf(a1[r], 0.0f);
        }
        __syncwarp();
#pragma unroll
        for (int r = 0; r < 4; r++) { cur0[r] = nx0[r]; cur1[r] = nx1[r]; }
    }

    __syncthreads();
    for (int idx = tid; idx < 16 * HH; idx += R_THREADS) {
        int r = idx >> 6, j = idx & 63;
        hT_out[(gb0 + r) * HH + j] = s_h[r][j];
    }
}

// ===========================================================================
// head kernels
// ===========================================================================
__global__ void bn1_stats_kernel(const float* __restrict__ hT) {
    const int f = blockIdx.x, tid = threadIdx.x;
    __shared__ float red[256];
    __shared__ float s_mu;

    float s = 0.0f;
    for (int b = tid; b < BB; b += 256) s += hT[b * HH + f];
    red[tid] = s;
    __syncthreads();
    for (int w = 128; w > 0; w >>= 1) {
        if (tid < w) red[tid] += red[tid + w];
        __syncthreads();
    }
    if (tid == 0) s_mu = red[0] * (1.0f / BB);
    __syncthreads();
    const float mu = s_mu;

    float s2 = 0.0f;
    for (int b = tid; b < BB; b += 256) {
        float v = hT[b * HH + f] - mu;
        s2 += v * v;
    }
    red[tid] = s2;
    __syncthreads();
    for (int w = 128; w > 0; w >>= 1) {
        if (tid < w) red[tid] += red[tid + w];
        __syncthreads();
    }
    if (tid == 0) {
        g_mu1[f] = mu;
        g_rs1[f] = rsqrtf(red[0] * (1.0f / BB) + 1e-5f);
    }
}

__global__ void fc1_kernel(const float* __restrict__ hT,
                           const float* __restrict__ g1, const float* __restrict__ be1,
                           const float* __restrict__ fW, const float* __restrict__ fb) {
    __shared__ float sW[H4 * HH];
    __shared__ float sc[HH], sh[HH], sb[H4];
    const int tid = threadIdx.x;
    for (int i = tid; i < H4 * HH; i += 256) sW[i] = fW[i];
    if (tid < HH) {
        float s = g_rs1[tid] * g1[tid];
        sc[tid] = s;
        sh[tid] = be1[tid] - g_mu1[tid] * s;
    }
    if (tid < H4) sb[tid] = fb[tid];
    __syncthreads();

    const int b = blockIdx.x * 256 + tid;
    float acc[H4];
#pragma unroll
    for (int o = 0; o < H4; o++) acc[o] = sb[o];
#pragma unroll 8
    for (int j = 0; j < HH; j++) {
        float v = fmaf(hT[b * HH + j], sc[j], sh[j]);
#pragma unroll
        for (int o = 0; o < H4; o++) acc[o] = fmaf(v, sW[o * HH + j], acc[o]);
    }
#pragma unroll
    for (int o = 0; o < H4; o++) g_z1[b * H4 + o] = fmaxf(acc[o], 0.0f);
}

__global__ void bn2_stats_kernel() {
    __shared__ float rs[8][H4], rq[8][H4];
    const int tid = threadIdx.x, lane = tid & 31, w = tid >> 5;

    float s[H4], q[H4];
#pragma unroll
    for (int i = 0; i < H4; i++) { s[i] = 0.0f; q[i] = 0.0f; }

    for (int b = tid; b < BB; b += 256) {
        const float4* p = (const float4*)(g_z1 + b * H4);
#pragma unroll
        for (int u = 0; u < 4; u++) {
            float4 v = p[u];
            s[u*4+0] += v.x; q[u*4+0] += v.x * v.x;
            s[u*4+1] += v.y; q[u*4+1] += v.y * v.y;
            s[u*4+2] += v.z; q[u*4+2] += v.z * v.z;
            s[u*4+3] += v.w; q[u*4+3] += v.w * v.w;
        }
    }
#pragma unroll
    for (int i = 0; i < H4; i++) {
#pragma unroll
        for (int d = 16; d > 0; d >>= 1) {
            s[i] += __shfl_xor_sync(0xFFFFFFFFu, s[i], d);
            q[i] += __shfl_xor_sync(0xFFFFFFFFu, q[i], d);
        }
    }
    if (lane == 0) {
#pragma unroll
        for (int i = 0; i < H4; i++) { rs[w][i] = s[i]; rq[w][i] = q[i]; }
    }
    __syncthreads();
    if (tid < H4) {
        float S = 0.0f, Q = 0.0f;
#pragma unroll
        for (int w2 = 0; w2 < 8; w2++) { S += rs[w2][tid]; Q += rq[w2][tid]; }
        float mu = S * (1.0f / BB);
        g_mu2[tid] = mu;
        g_rs2[tid] = rsqrtf(fmaxf(Q * (1.0f / BB) - mu * mu, 0.0f) + 1e-5f);
    }
}

__global__ void fc2_kernel(const float* __restrict__ g2, const float* __restrict__ be2,
                           const float* __restrict__ fW, const float* __restrict__ fb,
                           float* __restrict__ out) {
    __shared__ float sW[OO * H4];
    __shared__ float sc[H4], sh[H4], sb[OO];
    const int tid = threadIdx.x;
    if (tid < OO * H4) sW[tid] = fW[tid];
    if (tid < H4) {
        float s = g_rs2[tid] * g2[tid];
        sc[tid] = s;
        sh[tid] = be2[tid] - g_mu2[tid] * s;
    }
    if (tid < OO) sb[tid] = fb[tid];
    __syncthreads();

    const int b = blockIdx.x * 256 + tid;
    float z[H4];
#pragma unroll
    for (int o = 0; o < H4; o++) z[o] = fmaf(g_z1[b * H4 + o], sc[o], sh[o]);
#pragma unroll
    for (int c = 0; c < OO; c++) {
        float a = sb[c];
#pragma unroll
        for (int o = 0; o < H4; o++) a = fmaf(z[o], sW[c * H4 + o], a);
        out[b * OO + c] = a;
    }
}

// ---------------------------------------------------------------------------
// Launch. d_out layout: [0, B*O) = out; [B*O, B*O+B*H) = hT.
// ---------------------------------------------------------------------------
extern "C" void kernel_launch(void* const* d_in, const int* in_sizes, int n_in,
                              void* d_out, int out_size) {
    const float* x    = (const float*)d_in[0];
    const float* h0   = (const float*)d_in[1];
    const float* Wih  = (const float*)d_in[2];
    const float* Whh  = (const float*)d_in[3];
    const float* bih  = (const float*)d_in[4];
    const float* bhh  = (const float*)d_in[5];
    const float* bn1g = (const float*)d_in[6];
    const float* bn1b = (const float*)d_in[7];
    const float* fc1W = (const float*)d_in[8];
    const float* fc1b = (const float*)d_in[9];
    const float* bn2g = (const float*)d_in[10];
    const float* bn2b = (const float*)d_in[11];
    const float* fc2W = (const float*)d_in[12];
    const float* fc2b = (const float*)d_in[13];

    float* out = (float*)d_out;
    float* hT  = out + BB * OO;

    xp_gemm_kernel<<<G_GRID, G_THREADS>>>(x, Wih, bih, bhh);
    rnn_rec_kernel<<<R_GRID, R_THREADS>>>(h0, Whh, hT);
    bn1_stats_kernel<<<HH, 256>>>(hT);
    fc1_kernel<<<BB / 256, 256>>>(hT, bn1g, bn1b, fc1W, fc1b);
    bn2_stats_kernel<<<1, 256>>>();
    fc2_kernel<<<BB / 256, 256>>>(bn2g, bn2b, fc2W, fc2b, out);
}

// round 14
// speedup vs baseline: 2.1261x; 1.5180x over previous
#include <cuda_runtime.h>
#include <cstdint>

// Problem constants
#define BB 2048
#define SS 512
#define DD 128
#define HH 64
#define H4 16
#define OO 8

// Scratch (device globals — no runtime allocation allowed)
__device__ float g_z1[BB * H4];
__device__ float g_mu1[HH], g_rs1[HH];
__device__ float g_mu2[H4], g_rs2[H4];

// ===========================================================================
// bf16 split helpers (layouts validated by R12's passing GEMM)
// ===========================================================================
// pack {hi-half = bf16(b), lo-half = bf16(a)} and the residual pair
__device__ __forceinline__ void split_pair(float a, float b, uint32_t& h, uint32_t& l) {
    asm("cvt.rn.bf16x2.f32 %0, %1, %2;" : "=r"(h) : "f"(b), "f"(a));
    float ra = a - __uint_as_float(h << 16);
    float rb = b - __uint_as_float(h & 0xffff0000u);
    asm("cvt.rn.bf16x2.f32 %0, %1, %2;" : "=r"(l) : "f"(rb), "f"(ra));
}

__device__ __forceinline__ void mma_bf16(float c[4], const uint32_t a[4],
                                         uint32_t b0, uint32_t b1) {
    asm volatile(
        "mma.sync.aligned.m16n8k16.row.col.f32.bf16.bf16.f32 "
        "{%0,%1,%2,%3}, {%4,%5,%6,%7}, {%8,%9}, {%0,%1,%2,%3};"
        : "+f"(c[0]), "+f"(c[1]), "+f"(c[2]), "+f"(c[3])
        : "r"(a[0]), "r"(a[1]), "r"(a[2]), "r"(a[3]), "r"(b0), "r"(b1));
}

// ===========================================================================
// Fused RNN: h(t) = relu(x(t)@Wih^T + bias + h(t-1)@Whh^T), all on tensor MMA.
//
// 128 CTAs x 128 threads; CTA owns 16 batch rows (m16), warp w owns n-tiles
// {2w, 2w+1} (j cols [16w,16w+16)). Per step, per warp:
//   48 xp-MMAs (x: 8 k-chunks x 3 bf16-split products, Wih B-frags in regs)
// + 24 h-MMAs  (h: 4 k-chunks x 3 products, Whh B-frags in regs)
// into one C accumulator (init = bias). C -> relu -> in-register bf16 split
// gives exactly the A-fragment of k-chunk w for the next step (C n-tile pair
// == A k-chunk, same lane ownership) -> 32B STS to the h-frag exchange buffer.
// x is cp.async double-buffered (read once from DRAM) and cooperatively
// converted to shared A-frags.
//
// R14 fix: cp.async.wait_group only covers the CALLING thread's groups, so a
// __syncthreads() must sit between wait_group and any read of other threads'
// staged bytes (convert_x). R13 had wait -> read -> barrier, a visibility
// race that corrupted x tiles (rel_err 0.36). Now: wait -> barrier -> read.
// ===========================================================================
#define F_THREADS 128
#define F_GRID (BB / 16)   // 128

__global__ void __launch_bounds__(F_THREADS, 1)
rnn_fused_kernel(const float* __restrict__ x, const float* __restrict__ h0,
                 const float* __restrict__ Wih, const float* __restrict__ Whh,
                 const float* __restrict__ bih, const float* __restrict__ bhh,
                 float* __restrict__ hT_out) {
    __shared__ float s_xraw[2][16 * DD];      // raw x tile [r][d]      (2 x 8KB)
    __shared__ uint4 s_xfh[2][8 * 32];        // x A-frags hi [kc][lane] (2 x 4KB)
    __shared__ uint4 s_xfl[2][8 * 32];        // x A-frags lo            (2 x 4KB)
    __shared__ uint4 s_hfh[2][4 * 32];        // h A-frags hi            (2 x 2KB)
    __shared__ uint4 s_hfl[2][4 * 32];        // h A-frags lo            (2 x 2KB)

    const int tid  = threadIdx.x;
    const int w    = tid >> 5;
    const int lane = tid & 31;
    const int g    = lane >> 2;
    const int qb   = (lane & 3) * 2;
    const int gb0  = blockIdx.x * 16;

    // ---- B fragments in registers ----
    uint32_t wih_h[2][8][2], wih_l[2][8][2];
    uint32_t whh_h[2][4][2], whh_l[2][4][2];
    float bias0[2], bias1[2];
#pragma unroll
    for (int nt = 0; nt < 2; nt++) {
        const int n = 2 * w + nt;
        const float* wr = Wih + (n * 8 + g) * DD;
#pragma unroll
        for (int kc = 0; kc < 8; kc++) {
            const float* p = wr + kc * 16 + qb;
            split_pair(p[0], p[1], wih_h[nt][kc][0], wih_l[nt][kc][0]);
            split_pair(p[8], p[9], wih_h[nt][kc][1], wih_l[nt][kc][1]);
        }
        const float* hr = Whh + (n * 8 + g) * HH;
#pragma unroll
        for (int kc = 0; kc < 4; kc++) {
            const float* p = hr + kc * 16 + qb;
            split_pair(p[0], p[1], whh_h[nt][kc][0], whh_l[nt][kc][0]);
            split_pair(p[8], p[9], whh_h[nt][kc][1], whh_l[nt][kc][1]);
        }
        bias0[nt] = bih[n * 8 + qb]     + bhh[n * 8 + qb];
        bias1[nt] = bih[n * 8 + qb + 1] + bhh[n * 8 + qb + 1];
    }

    // ---- h(-1) = h0 -> frag chunk w into s_hf[0] ----
    {
        const float* hb = h0 + (size_t)gb0 * HH;
        uint4 hh, hl;
        split_pair(hb[g * HH + 16 * w + qb],        hb[g * HH + 16 * w + qb + 1],       hh.x, hl.x);
        split_pair(hb[(g + 8) * HH + 16 * w + qb],  hb[(g + 8) * HH + 16 * w + qb + 1], hh.y, hl.y);
        split_pair(hb[g * HH + 16 * w + 8 + qb],       hb[g * HH + 16 * w + 8 + qb + 1],       hh.z, hl.z);
        split_pair(hb[(g + 8) * HH + 16 * w + 8 + qb], hb[(g + 8) * HH + 16 * w + 8 + qb + 1], hh.w, hl.w);
        s_hfh[0][w * 32 + lane] = hh;
        s_hfl[0][w * 32 + lane] = hl;
    }

    // ---- cp.async stage of x(t) tile (8KB: 4 x 16B per thread) ----
    auto stage_x = [&](int buf, int t) {
        uint32_t dst0;
        asm("{ .reg .u64 a; cvta.to.shared.u64 a, %1; cvt.u32.u64 %0, a; }"
            : "=r"(dst0) : "l"(&s_xraw[buf][0]));
#pragma unroll
        for (int i = 0; i < 4; i++) {
            int u = tid * 4 + i;           // 512 units of 16B
            int r = u >> 5, c16 = u & 31;
            const float* src = x + ((size_t)(gb0 + r) * SS + t) * DD + c16 * 4;
            asm volatile("cp.async.cg.shared.global [%0], [%1], 16;"
                         :: "r"(dst0 + u * 16), "l"(src));
        }
        asm volatile("cp.async.commit_group;" ::: "memory");
    };

    stage_x(0, 0);
    asm volatile("cp.async.wait_group 0;" ::: "memory");
    __syncthreads();   // wait -> barrier -> read (all threads' groups visible)

    // convert x(t) -> s_xf[buf]; thread handles frag slots tid and tid+128
    auto convert_x = [&](int buf) {
#pragma unroll
        for (int s = 0; s < 2; s++) {
            int slot = tid + s * 128;
            int kc = slot >> 5, l = slot & 31;
            int g2 = l >> 2, q2 = (l & 3) * 2;
            const float* xr = &s_xraw[buf][0];
            float2 p0 = *(const float2*)(xr + g2 * DD + kc * 16 + q2);
            float2 p1 = *(const float2*)(xr + (g2 + 8) * DD + kc * 16 + q2);
            float2 p2 = *(const float2*)(xr + g2 * DD + kc * 16 + q2 + 8);
            float2 p3 = *(const float2*)(xr + (g2 + 8) * DD + kc * 16 + q2 + 8);
            uint4 fh, fl;
            split_pair(p0.x, p0.y, fh.x, fl.x);
            split_pair(p1.x, p1.y, fh.y, fl.y);
            split_pair(p2.x, p2.y, fh.z, fl.z);
            split_pair(p3.x, p3.y, fh.w, fl.w);
            s_xfh[buf][slot] = fh;
            s_xfl[buf][slot] = fl;
        }
    };

    convert_x(0);
    stage_x(1, 1);
    __syncthreads();

    // C = bias + xp(0)
    float C[2][4];
    auto xp_mma = [&](float c[2][4], int buf) {
#pragma unroll
        for (int nt = 0; nt < 2; nt++) {
            c[nt][0] = bias0[nt]; c[nt][1] = bias1[nt];
            c[nt][2] = bias0[nt]; c[nt][3] = bias1[nt];
        }
#pragma unroll
        for (int kc = 0; kc < 8; kc++) {
            uint4 ahv = s_xfh[buf][kc * 32 + lane];
            uint4 alv = s_xfl[buf][kc * 32 + lane];
            uint32_t ah[4] = {ahv.x, ahv.y, ahv.z, ahv.w};
            uint32_t al[4] = {alv.x, alv.y, alv.z, alv.w};
#pragma unroll
            for (int nt = 0; nt < 2; nt++) {
                mma_bf16(c[nt], ah, wih_h[nt][kc][0], wih_h[nt][kc][1]);
                mma_bf16(c[nt], al, wih_h[nt][kc][0], wih_h[nt][kc][1]);
                mma_bf16(c[nt], ah, wih_l[nt][kc][0], wih_l[nt][kc][1]);
            }
        }
    };
    xp_mma(C, 0);

    int pb = 0, xb = 1;
    for (int i = 0; i < SS; i++) {
        // ---- h-MMA: C += h(i-1) @ Whh^T ----
#pragma unroll
        for (int kc = 0; kc < 4; kc++) {
            uint4 ahv = s_hfh[pb][kc * 32 + lane];
            uint4 alv = s_hfl[pb][kc * 32 + lane];
            uint32_t ah[4] = {ahv.x, ahv.y, ahv.z, ahv.w};
            uint32_t al[4] = {alv.x, alv.y, alv.z, alv.w};
#pragma unroll
            for (int nt = 0; nt < 2; nt++) {
                mma_bf16(C[nt], ah, whh_h[nt][kc][0], whh_h[nt][kc][1]);
                mma_bf16(C[nt], al, whh_h[nt][kc][0], whh_h[nt][kc][1]);
                mma_bf16(C[nt], ah, whh_l[nt][kc][0], whh_l[nt][kc][1]);
            }
        }
        // ---- relu; C n-tile pair == next-step A k-chunk w (in-register) ----
        float v00 = fmaxf(C[0][0], 0.0f), v01 = fmaxf(C[0][1], 0.0f);
        float v02 = fmaxf(C[0][2], 0.0f), v03 = fmaxf(C[0][3], 0.0f);
        float v10 = fmaxf(C[1][0], 0.0f), v11 = fmaxf(C[1][1], 0.0f);
        float v12 = fmaxf(C[1][2], 0.0f), v13 = fmaxf(C[1][3], 0.0f);

        if (i == SS - 1) {
            // write hT: rows g / g+8, cols (2w+nt)*8 + qb (+1)
            float* hb = hT_out + (size_t)gb0 * HH;
            *(float2*)(hb + g * HH + (2 * w) * 8 + qb)       = make_float2(v00, v01);
            *(float2*)(hb + (g + 8) * HH + (2 * w) * 8 + qb) = make_float2(v02, v03);
            *(float2*)(hb + g * HH + (2 * w + 1) * 8 + qb)       = make_float2(v10, v11);
            *(float2*)(hb + (g + 8) * HH + (2 * w + 1) * 8 + qb) = make_float2(v12, v13);
            break;
        }

        {   // split h(i) -> A-frag chunk w for next step
            uint4 hh, hl;
            split_pair(v00, v01, hh.x, hl.x);
            split_pair(v02, v03, hh.y, hl.y);
            split_pair(v10, v11, hh.z, hl.z);
            split_pair(v12, v13, hh.w, hl.w);
            s_hfh[pb ^ 1][w * 32 + lane] = hh;
            s_hfl[pb ^ 1][w * 32 + lane] = hl;
        }

        // ---- x pipeline: wait x(i+1), BARRIER (visibility), convert, prefetch
        asm volatile("cp.async.wait_group 0;" ::: "memory");
        __syncthreads();   // R14 fix: other threads' cp.async data now visible

        convert_x(xb);
        if (i + 2 < SS) stage_x(xb ^ 1, i + 2);

        __syncthreads();

        // ---- xp-MMA for step i+1 ----
        xp_mma(C, xb);

        pb ^= 1;
        xb ^= 1;
    }
}

// ===========================================================================
// head kernels (unchanged — proven)
// ===========================================================================
__global__ void bn1_stats_kernel(const float* __restrict__ hT) {
    const int f = blockIdx.x, tid = threadIdx.x;
    __shared__ float red[256];
    __shared__ float s_mu;

    float s = 0.0f;
    for (int b = tid; b < BB; b += 256) s += hT[b * HH + f];
    red[tid] = s;
    __syncthreads();
    for (int w = 128; w > 0; w >>= 1) {
        if (tid < w) red[tid] += red[tid + w];
        __syncthreads();
    }
    if (tid == 0) s_mu = red[0] * (1.0f / BB);
    __syncthreads();
    const float mu = s_mu;

    float s2 = 0.0f;
    for (int b = tid; b < BB; b += 256) {
        float v = hT[b * HH + f] - mu;
        s2 += v * v;
    }
    red[tid] = s2;
    __syncthreads();
    for (int w = 128; w > 0; w >>= 1) {
        if (tid < w) red[tid] += red[tid + w];
        __syncthreads();
    }
    if (tid == 0) {
        g_mu1[f] = mu;
        g_rs1[f] = rsqrtf(red[0] * (1.0f / BB) + 1e-5f);
    }
}

__global__ void fc1_kernel(const float* __restrict__ hT,
                           const float* __restrict__ g1, const float* __restrict__ be1,
                           const float* __restrict__ fW, const float* __restrict__ fb) {
    __shared__ float sW[H4 * HH];
    __shared__ float sc[HH], sh[HH], sb[H4];
    const int tid = threadIdx.x;
    for (int i = tid; i < H4 * HH; i += 256) sW[i] = fW[i];
    if (tid < HH) {
        float s = g_rs1[tid] * g1[tid];
        sc[tid] = s;
        sh[tid] = be1[tid] - g_mu1[tid] * s;
    }
    if (tid < H4) sb[tid] = fb[tid];
    __syncthreads();

    const int b = blockIdx.x * 256 + tid;
    float acc[H4];
#pragma unroll
    for (int o = 0; o < H4; o++) acc[o] = sb[o];
#pragma unroll 8
    for (int j = 0; j < HH; j++) {
        float v = fmaf(hT[b * HH + j], sc[j], sh[j]);
#pragma unroll
        for (int o = 0; o < H4; o++) acc[o] = fmaf(v, sW[o * HH + j], acc[o]);
    }
#pragma unroll
    for (int o = 0; o < H4; o++) g_z1[b * H4 + o] = fmaxf(acc[o], 0.0f);
}

__global__ void bn2_stats_kernel() {
    __shared__ float rs[8][H4], rq[8][H4];
    const int tid = threadIdx.x, lane = tid & 31, w = tid >> 5;

    float s[H4], q[H4];
#pragma unroll
    for (int i = 0; i < H4; i++) { s[i] = 0.0f; q[i] = 0.0f; }

    for (int b = tid; b < BB; b += 256) {
        const float4* p = (const float4*)(g_z1 + b * H4);
#pragma unroll
        for (int u = 0; u < 4; u++) {
            float4 v = p[u];
            s[u*4+0] += v.x; q[u*4+0] += v.x * v.x;
            s[u*4+1] += v.y; q[u*4+1] += v.y * v.y;
            s[u*4+2] += v.z; q[u*4+2] += v.z * v.z;
            s[u*4+3] += v.w; q[u*4+3] += v.w * v.w;
        }
    }
#pragma unroll
    for (int i = 0; i < H4; i++) {
#pragma unroll
        for (int d = 16; d > 0; d >>= 1) {
            s[i] += __shfl_xor_sync(0xFFFFFFFFu, s[i], d);
            q[i] += __shfl_xor_sync(0xFFFFFFFFu, q[i], d);
        }
    }
    if (lane == 0) {
#pragma unroll
        for (int i = 0; i < H4; i++) { rs[w][i] = s[i]; rq[w][i] = q[i]; }
    }
    __syncthreads();
    if (tid < H4) {
        float S = 0.0f, Q = 0.0f;
#pragma unroll
        for (int w2 = 0; w2 < 8; w2++) { S += rs[w2][tid]; Q += rq[w2][tid]; }
        float mu = S * (1.0f / BB);
        g_mu2[tid] = mu;
        g_rs2[tid] = rsqrtf(fmaxf(Q * (1.0f / BB) - mu * mu, 0.0f) + 1e-5f);
    }
}

__global__ void fc2_kernel(const float* __restrict__ g2, const float* __restrict__ be2,
                           const float* __restrict__ fW, const float* __restrict__ fb,
                           float* __restrict__ out) {
    __shared__ float sW[OO * H4];
    __shared__ float sc[H4], sh[H4], sb[OO];
    const int tid = threadIdx.x;
    if (tid < OO * H4) sW[tid] = fW[tid];
    if (tid < H4) {
        float s = g_rs2[tid] * g2[tid];
        sc[tid] = s;
        sh[tid] = be2[tid] - g_mu2[tid] * s;
    }
    if (tid < OO) sb[tid] = fb[tid];
    __syncthreads();

    const int b = blockIdx.x * 256 + tid;
    float z[H4];
#pragma unroll
    for (int o = 0; o < H4; o++) z[o] = fmaf(g_z1[b * H4 + o], sc[o], sh[o]);
#pragma unroll
    for (int c = 0; c < OO; c++) {
        float a = sb[c];
#pragma unroll
        for (int o = 0; o < H4; o++) a = fmaf(z[o], sW[c * H4 + o], a);
        out[b * OO + c] = a;
    }
}

// ---------------------------------------------------------------------------
// Launch. d_out layout: [0, B*O) = out; [B*O, B*O+B*H) = hT.
// ---------------------------------------------------------------------------
extern "C" void kernel_launch(void* const* d_in, const int* in_sizes, int n_in,
                              void* d_out, int out_size) {
    const float* x    = (const float*)d_in[0];
    const float* h0   = (const float*)d_in[1];
    const float* Wih  = (const float*)d_in[2];
    const float* Whh  = (const float*)d_in[3];
    const float* bih  = (const float*)d_in[4];
    const float* bhh  = (const float*)d_in[5];
    const float* bn1g = (const float*)d_in[6];
    const float* bn1b = (const float*)d_in[7];
    const float* fc1W = (const float*)d_in[8];
    const float* fc1b = (const float*)d_in[9];
    const float* bn2g = (const float*)d_in[10];
    const float* bn2b = (const float*)d_in[11];
    const float* fc2W = (const float*)d_in[12];
    const float* fc2b = (const float*)d_in[13];

    float* out = (float*)d_out;
    float* hT  = out + BB * OO;

    rnn_fused_kernel<<<F_GRID, F_THREADS>>>(x, h0, Wih, Whh, bih, bhh, hT);
    bn1_stats_kernel<<<HH, 256>>>(hT);
    fc1_kernel<<<BB / 256, 256>>>(hT, bn1g, bn1b, fc1W, fc1b);
    bn2_stats_kernel<<<1, 256>>>();
    fc2_kernel<<<BB / 256, 256>>>(bn2g, bn2b, fc2W, fc2b, out);
}

// round 16
// speedup vs baseline: 2.5541x; 1.2013x over previous
#include <cuda_runtime.h>
#include <cstdint>

// Problem constants
#define BB 2048
#define SS 512
#define DD 128
#define HH 64
#define H4 16
#define OO 8

// Scratch (device globals — no runtime allocation allowed)
__device__ float g_z1[BB * H4];
__device__ float g_mu1[HH], g_rs1[HH];
__device__ float g_mu2[H4], g_rs2[H4];

// ===========================================================================
// bf16 split helpers (layouts validated by R12/R14)
// ===========================================================================
__device__ __forceinline__ void split_pair(float a, float b, uint32_t& h, uint32_t& l) {
    asm("cvt.rn.bf16x2.f32 %0, %1, %2;" : "=r"(h) : "f"(b), "f"(a));
    float ra = a - __uint_as_float(h << 16);
    float rb = b - __uint_as_float(h & 0xffff0000u);
    asm("cvt.rn.bf16x2.f32 %0, %1, %2;" : "=r"(l) : "f"(rb), "f"(ra));
}

__device__ __forceinline__ void mma_bf16(float c[4], const uint32_t a[4],
                                         uint32_t b0, uint32_t b1) {
    asm volatile(
        "mma.sync.aligned.m16n8k16.row.col.f32.bf16.bf16.f32 "
        "{%0,%1,%2,%3}, {%4,%5,%6,%7}, {%8,%9}, {%0,%1,%2,%3};"
        : "+f"(c[0]), "+f"(c[1]), "+f"(c[2]), "+f"(c[3])
        : "r"(a[0]), "r"(a[1]), "r"(a[2]), "r"(a[3]), "r"(b0), "r"(b1));
}

// ===========================================================================
// Fused RNN: h(t) = relu(x(t)@Wih^T + bias + h(t-1)@Whh^T) on tensor MMA.
//
// R15 vs R14:
//  - 3 independent accumulator chains per n-tile (per split product), summed
//    at relu: h-MMA critical path 12 -> 4, xp 24 -> 8 chained MMAs.
//  - cp.async prefetch depth 2 (3 raw buffers, wait_group 1; wait_group 0 at
//    the final convert where the needed tile is the newest group).
//  - stage_x issued before convert_x each step.
// Barrier structure (wait -> bar -> read) identical to R14 (proven).
// ===========================================================================
#define F_THREADS 128
#define F_GRID (BB / 16)   // 128

__global__ void __launch_bounds__(F_THREADS, 1)
rnn_fused_kernel(const float* __restrict__ x, const float* __restrict__ h0,
                 const float* __restrict__ Wih, const float* __restrict__ Whh,
                 const float* __restrict__ bih, const float* __restrict__ bhh,
                 float* __restrict__ hT_out) {
    __shared__ float s_xraw[3][16 * DD];      // raw x tiles (3 x 8KB)
    __shared__ uint4 s_xfh[2][8 * 32];        // x A-frags hi (2 x 4KB)
    __shared__ uint4 s_xfl[2][8 * 32];        // x A-frags lo (2 x 4KB)
    __shared__ uint4 s_hfh[2][4 * 32];        // h A-frags hi (2 x 2KB)
    __shared__ uint4 s_hfl[2][4 * 32];        // h A-frags lo (2 x 2KB)

    const int tid  = threadIdx.x;
    const int w    = tid >> 5;
    const int lane = tid & 31;
    const int g    = lane >> 2;
    const int qb   = (lane & 3) * 2;
    const int gb0  = blockIdx.x * 16;

    // ---- B fragments in registers ----
    uint32_t wih_h[2][8][2], wih_l[2][8][2];
    uint32_t whh_h[2][4][2], whh_l[2][4][2];
    float bias0[2], bias1[2];
#pragma unroll
    for (int nt = 0; nt < 2; nt++) {
        const int n = 2 * w + nt;
        const float* wr = Wih + (n * 8 + g) * DD;
#pragma unroll
        for (int kc = 0; kc < 8; kc++) {
            const float* p = wr + kc * 16 + qb;
            split_pair(p[0], p[1], wih_h[nt][kc][0], wih_l[nt][kc][0]);
            split_pair(p[8], p[9], wih_h[nt][kc][1], wih_l[nt][kc][1]);
        }
        const float* hr = Whh + (n * 8 + g) * HH;
#pragma unroll
        for (int kc = 0; kc < 4; kc++) {
            const float* p = hr + kc * 16 + qb;
            split_pair(p[0], p[1], whh_h[nt][kc][0], whh_l[nt][kc][0]);
            split_pair(p[8], p[9], whh_h[nt][kc][1], whh_l[nt][kc][1]);
        }
        bias0[nt] = bih[n * 8 + qb]     + bhh[n * 8 + qb];
        bias1[nt] = bih[n * 8 + qb + 1] + bhh[n * 8 + qb + 1];
    }

    // ---- h(-1) = h0 -> frag chunk w into s_hf[0] ----
    {
        const float* hb = h0 + (size_t)gb0 * HH;
        uint4 hh, hl;
        split_pair(hb[g * HH + 16 * w + qb],        hb[g * HH + 16 * w + qb + 1],       hh.x, hl.x);
        split_pair(hb[(g + 8) * HH + 16 * w + qb],  hb[(g + 8) * HH + 16 * w + qb + 1], hh.y, hl.y);
        split_pair(hb[g * HH + 16 * w + 8 + qb],       hb[g * HH + 16 * w + 8 + qb + 1],       hh.z, hl.z);
        split_pair(hb[(g + 8) * HH + 16 * w + 8 + qb], hb[(g + 8) * HH + 16 * w + 8 + qb + 1], hh.w, hl.w);
        s_hfh[0][w * 32 + lane] = hh;
        s_hfl[0][w * 32 + lane] = hl;
    }

    // ---- cp.async stage of x(t) tile into raw buf (8KB: 4 x 16B/thread) ----
    auto stage_x = [&](int buf, int t) {
        uint32_t dst0;
        asm("{ .reg .u64 a; cvta.to.shared.u64 a, %1; cvt.u32.u64 %0, a; }"
            : "=r"(dst0) : "l"(&s_xraw[buf][0]));
#pragma unroll
        for (int i = 0; i < 4; i++) {
            int u = tid * 4 + i;           // 512 units of 16B
            int r = u >> 5, c16 = u & 31;
            const float* src = x + ((size_t)(gb0 + r) * SS + t) * DD + c16 * 4;
            asm volatile("cp.async.cg.shared.global [%0], [%1], 16;"
                         :: "r"(dst0 + u * 16), "l"(src));
        }
        asm volatile("cp.async.commit_group;" ::: "memory");
    };

    // convert raw x -> A-frags; thread handles frag slots tid and tid+128
    auto convert_x = [&](int rawbuf, int fbuf) {
#pragma unroll
        for (int s = 0; s < 2; s++) {
            int slot = tid + s * 128;
            int kc = slot >> 5, l = slot & 31;
            int g2 = l >> 2, q2 = (l & 3) * 2;
            const float* xr = &s_xraw[rawbuf][0];
            float2 p0 = *(const float2*)(xr + g2 * DD + kc * 16 + q2);
            float2 p1 = *(const float2*)(xr + (g2 + 8) * DD + kc * 16 + q2);
            float2 p2 = *(const float2*)(xr + g2 * DD + kc * 16 + q2 + 8);
            float2 p3 = *(const float2*)(xr + (g2 + 8) * DD + kc * 16 + q2 + 8);
            uint4 fh, fl;
            split_pair(p0.x, p0.y, fh.x, fl.x);
            split_pair(p1.x, p1.y, fh.y, fl.y);
            split_pair(p2.x, p2.y, fh.z, fl.z);
            split_pair(p3.x, p3.y, fh.w, fl.w);
            s_xfh[fbuf][slot] = fh;
            s_xfl[fbuf][slot] = fl;
        }
    };

    // ---- prologue: stage t=0,1,2; convert t=0 ----
    stage_x(0, 0);
    stage_x(1, 1);
    stage_x(2, 2);
    asm volatile("cp.async.wait_group 0;" ::: "memory");
    __syncthreads();               // wait -> barrier -> read
    convert_x(0, 0);
    __syncthreads();

    // C accumulators: 3 independent chains per n-tile (AhBh / AlBh / AhBl)
    float C[2][3][4];
    auto xp_mma = [&](int fbuf) {
#pragma unroll
        for (int nt = 0; nt < 2; nt++) {
            C[nt][0][0] = bias0[nt]; C[nt][0][1] = bias1[nt];
            C[nt][0][2] = bias0[nt]; C[nt][0][3] = bias1[nt];
#pragma unroll
            for (int i = 0; i < 4; i++) { C[nt][1][i] = 0.0f; C[nt][2][i] = 0.0f; }
        }
#pragma unroll
        for (int kc = 0; kc < 8; kc++) {
            uint4 ahv = s_xfh[fbuf][kc * 32 + lane];
            uint4 alv = s_xfl[fbuf][kc * 32 + lane];
            uint32_t ah[4] = {ahv.x, ahv.y, ahv.z, ahv.w};
            uint32_t al[4] = {alv.x, alv.y, alv.z, alv.w};
#pragma unroll
            for (int nt = 0; nt < 2; nt++) {
                mma_bf16(C[nt][0], ah, wih_h[nt][kc][0], wih_h[nt][kc][1]);
                mma_bf16(C[nt][1], al, wih_h[nt][kc][0], wih_h[nt][kc][1]);
                mma_bf16(C[nt][2], ah, wih_l[nt][kc][0], wih_l[nt][kc][1]);
            }
        }
    };
    xp_mma(0);   // C = bias + xp(0)

    int pb = 0, xb = 1;
    for (int i = 0; i < SS; i++) {
        // ---- h-MMA: C += h(i-1) @ Whh^T (3 chains of 4) ----
#pragma unroll
        for (int kc = 0; kc < 4; kc++) {
            uint4 ahv = s_hfh[pb][kc * 32 + lane];
            uint4 alv = s_hfl[pb][kc * 32 + lane];
            uint32_t ah[4] = {ahv.x, ahv.y, ahv.z, ahv.w};
            uint32_t al[4] = {alv.x, alv.y, alv.z, alv.w};
#pragma unroll
            for (int nt = 0; nt < 2; nt++) {
                mma_bf16(C[nt][0], ah, whh_h[nt][kc][0], whh_h[nt][kc][1]);
                mma_bf16(C[nt][1], al, whh_h[nt][kc][0], whh_h[nt][kc][1]);
                mma_bf16(C[nt][2], ah, whh_l[nt][kc][0], whh_l[nt][kc][1]);
            }
        }
        // ---- sum chains + relu ----
        float v00 = fmaxf((C[0][0][0] + C[0][1][0]) + C[0][2][0], 0.0f);
        float v01 = fmaxf((C[0][0][1] + C[0][1][1]) + C[0][2][1], 0.0f);
        float v02 = fmaxf((C[0][0][2] + C[0][1][2]) + C[0][2][2], 0.0f);
        float v03 = fmaxf((C[0][0][3] + C[0][1][3]) + C[0][2][3], 0.0f);
        float v10 = fmaxf((C[1][0][0] + C[1][1][0]) + C[1][2][0], 0.0f);
        float v11 = fmaxf((C[1][0][1] + C[1][1][1]) + C[1][2][1], 0.0f);
        float v12 = fmaxf((C[1][0][2] + C[1][1][2]) + C[1][2][2], 0.0f);
        float v13 = fmaxf((C[1][0][3] + C[1][1][3]) + C[1][2][3], 0.0f);

        if (i == SS - 1) {
            float* hb = hT_out + (size_t)gb0 * HH;
            *(float2*)(hb + g * HH + (2 * w) * 8 + qb)       = make_float2(v00, v01);
            *(float2*)(hb + (g + 8) * HH + (2 * w) * 8 + qb) = make_float2(v02, v03);
            *(float2*)(hb + g * HH + (2 * w + 1) * 8 + qb)       = make_float2(v10, v11);
            *(float2*)(hb + (g + 8) * HH + (2 * w + 1) * 8 + qb) = make_float2(v12, v13);
            break;
        }

        {   // split h(i) -> A-frag chunk w for next step
            uint4 hh, hl;
            split_pair(v00, v01, hh.x, hl.x);
            split_pair(v02, v03, hh.y, hl.y);
            split_pair(v10, v11, hh.z, hl.z);
            split_pair(v12, v13, hh.w, hl.w);
            s_hfh[pb ^ 1][w * 32 + lane] = hh;
            s_hfl[pb ^ 1][w * 32 + lane] = hl;
        }

        // ---- x pipeline: wait x(i+1) (staged 2 steps ago), barrier, then
        //      stage x(i+3) and convert x(i+1). wait_group 1 suffices except
        //      at i==SS-2 where x(i+1) is the newest (last-staged) group.
        if (i >= SS - 2) {
            asm volatile("cp.async.wait_group 0;" ::: "memory");
        } else {
            asm volatile("cp.async.wait_group 1;" ::: "memory");
        }
        __syncthreads();   // visibility: other threads' cp.async + h-frags

        if (i + 3 < SS) stage_x((i + 3) % 3, i + 3);
        convert_x((i + 1) % 3, xb);

        __syncthreads();

        // ---- xp-MMA for step i+1 (re-inits the 3 chains with bias) ----
        xp_mma(xb);

        pb ^= 1;
        xb ^= 1;
    }
}

// ===========================================================================
// head kernels
// ===========================================================================
__global__ void bn1_stats_kernel(const float* __restrict__ hT) {
    const int f = blockIdx.x, tid = threadIdx.x;
    __shared__ float red[256];
    __shared__ float s_mu;

    float s = 0.0f;
    for (int b = tid; b < BB; b += 256) s += hT[b * HH + f];
    red[tid] = s;
    __syncthreads();
    for (int w = 128; w > 0; w >>= 1) {
        if (tid < w) red[tid] += red[tid + w];
        __syncthreads();
    }
    if (tid == 0) s_mu = red[0] * (1.0f / BB);
    __syncthreads();
    const float mu = s_mu;

    float s2 = 0.0f;
    for (int b = tid; b < BB; b += 256) {
        float v = hT[b * HH + f] - mu;
        s2 += v * v;
    }
    red[tid] = s2;
    __syncthreads();
    for (int w = 128; w > 0; w >>= 1) {
        if (tid < w) red[tid] += red[tid + w];
        __syncthreads();
    }
    if (tid == 0) {
        g_mu1[f] = mu;
        g_rs1[f] = rsqrtf(red[0] * (1.0f / BB) + 1e-5f);
    }
}

__global__ void fc1_kernel(const float* __restrict__ hT,
                           const float* __restrict__ g1, const float* __restrict__ be1,
                           const float* __restrict__ fW, const float* __restrict__ fb) {
    __shared__ float sW[H4 * HH];
    __shared__ float sc[HH], sh[HH], sb[H4];
    const int tid = threadIdx.x;
    for (int i = tid; i < H4 * HH; i += 128) sW[i] = fW[i];
    if (tid < HH) {
        float s = g_rs1[tid] * g1[tid];
        sc[tid] = s;
        sh[tid] = be1[tid] - g_mu1[tid] * s;
    }
    if (tid < H4) sb[tid] = fb[tid];
    __syncthreads();

    const int b = blockIdx.x * 128 + tid;
    float acc[H4];
#pragma unroll
    for (int o = 0; o < H4; o++) acc[o] = sb[o];
#pragma unroll 8
    for (int j = 0; j < HH; j++) {
        float v = fmaf(hT[b * HH + j], sc[j], sh[j]);
#pragma unroll
        for (int o = 0; o < H4; o++) acc[o] = fmaf(v, sW[o * HH + j], acc[o]);
    }
#pragma unroll
    for (int o = 0; o < H4; o++) g_z1[b * H4 + o] = fmaxf(acc[o], 0.0f);
}

__global__ void bn2_stats_kernel() {
    __shared__ float rs[8][H4], rq[8][H4];
    const int tid = threadIdx.x, lane = tid & 31, w = tid >> 5;

    float s[H4], q[H4];
#pragma unroll
    for (int i = 0; i < H4; i++) { s[i] = 0.0f; q[i] = 0.0f; }

    for (int b = tid; b < BB; b += 256) {
        const float4* p = (const float4*)(g_z1 + b * H4);
#pragma unroll
        for (int u = 0; u < 4; u++) {
            float4 v = p[u];
            s[u*4+0] += v.x; q[u*4+0] += v.x * v.x;
            s[u*4+1] += v.y; q[u*4+1] += v.y * v.y;
            s[u*4+2] += v.z; q[u*4+2] += v.z * v.z;
            s[u*4+3] += v.w; q[u*4+3] += v.w * v.w;
        }
    }
#pragma unroll
    for (int i = 0; i < H4; i++) {
#pragma unroll
        for (int d = 16; d > 0; d >>= 1) {
            s[i] += __shfl_xor_sync(0xFFFFFFFFu, s[i], d);
            q[i] += __shfl_xor_sync(0xFFFFFFFFu, q[i], d);
        }
    }
    if (lane == 0) {
#pragma unroll
        for (int i = 0; i < H4; i++) { rs[w][i] = s[i]; rq[w][i] = q[i]; }
    }
    __syncthreads();
    if (tid < H4) {
        float S = 0.0f, Q = 0.0f;
#pragma unroll
        for (int w2 = 0; w2 < 8; w2++) { S += rs[w2][tid]; Q += rq[w2][tid]; }
        float mu = S * (1.0f / BB);
        g_mu2[tid] = mu;
        g_rs2[tid] = rsqrtf(fmaxf(Q * (1.0f / BB) - mu * mu, 0.0f) + 1e-5f);
    }
}

__global__ void fc2_kernel(const float* __restrict__ g2, const float* __restrict__ be2,
                           const float* __restrict__ fW, const float* __restrict__ fb,
                           float* __restrict__ out) {
    __shared__ float sW[OO * H4];
    __shared__ float sc[H4], sh[H4], sb[OO];
    const int tid = threadIdx.x;
    if (tid < OO * H4) sW[tid] = fW[tid];
    if (tid < H4) {
        float s = g_rs2[tid] * g2[tid];
        sc[tid] = s;
        sh[tid] = be2[tid] - g_mu2[tid] * s;
    }
    if (tid < OO) sb[tid] = fb[tid];
    __syncthreads();

    const int b = blockIdx.x * 256 + tid;
    float z[H4];
#pragma unroll
    for (int o = 0; o < H4; o++) z[o] = fmaf(g_z1[b * H4 + o], sc[o], sh[o]);
#pragma unroll
    for (int c = 0; c < OO; c++) {
        float a = sb[c];
#pragma unroll
        for (int o = 0; o < H4; o++) a = fmaf(z[o], sW[c * H4 + o], a);
        out[b * OO + c] = a;
    }
}

// ---------------------------------------------------------------------------
// Launch. d_out layout: [0, B*O) = out; [B*O, B*O+B*H) = hT.
// ---------------------------------------------------------------------------
extern "C" void kernel_launch(void* const* d_in, const int* in_sizes, int n_in,
                              void* d_out, int out_size) {
    const float* x    = (const float*)d_in[0];
    const float* h0   = (const float*)d_in[1];
    const float* Wih  = (const float*)d_in[2];
    const float* Whh  = (const float*)d_in[3];
    const float* bih  = (const float*)d_in[4];
    const float* bhh  = (const float*)d_in[5];
    const float* bn1g = (const float*)d_in[6];
    const float* bn1b = (const float*)d_in[7];
    const float* fc1W = (const float*)d_in[8];
    const float* fc1b = (const float*)d_in[9];
    const float* bn2g = (const float*)d_in[10];
    const float* bn2b = (const float*)d_in[11];
    const float* fc2W = (const float*)d_in[12];
    const float* fc2b = (const float*)d_in[13];

    float* out = (float*)d_out;
    float* hT  = out + BB * OO;

    rnn_fused_kernel<<<F_GRID, F_THREADS>>>(x, h0, Wih, Whh, bih, bhh, hT);
    bn1_stats_kernel<<<HH, 256>>>(hT);
    fc1_kernel<<<BB / 128, 128>>>(hT, bn1g, bn1b, fc1W, fc1b);
    bn2_stats_kernel<<<1, 256>>>();
    fc2_kernel<<<BB / 256, 256>>>(bn2g, bn2b, fc2W, fc2b, out);
}